// round 16
// baseline (speedup 1.0000x reference)
#include <cuda_runtime.h>
#include <cstdint>

// TRFAligner: out[d, t] = sum over (seq, k) with sourceIdx[seq] + k == t of TRFs[seq, k, d]
// TRFs: (nSeq, nWin, OUTD) fp32; out: (OUTD, nRealLen) fp32. sourceIdx sorted.
// TILE_T=32 / 256 threads / 4 rows per warp. Per (CTA, seq) the needed TRF rows
// are CONTIGUOUS in GMEM (klo..khi of that seq's window, <=16KB), so each stage
// is ONE cp.async.bulk (UBLKCP) issued by tid0 into a 3-deep mbarrier ring,
// replacing ~1024 per-thread LDGSTS per seq. Consumers try_wait + LDS.128.
// No atomics.

#define OUTD      128
#define TILE_T    32
#define ROWSTRIDE 132                 // transpose tile row stride (floats)
#define NWARPS    8
#define NTHREADS  (NWARPS * 32)
#define ROWS_PW   (TILE_T / NWARPS)   // 4 rows per warp: tt = w + 8*r
#define CHUNK     64
#define NSTAGE    3
#define STAGE_B   (TILE_T * 32 * 16)  // 16384 bytes per stage (max 32 rows x 512B)

__device__ __forceinline__ void mbar_init(uint32_t mbar, uint32_t count) {
    asm volatile("mbarrier.init.shared.b64 [%0], %1;" :: "r"(mbar), "r"(count) : "memory");
}
__device__ __forceinline__ void mbar_expect_tx(uint32_t mbar, uint32_t bytes) {
    asm volatile("mbarrier.arrive.expect_tx.shared.b64 _, [%0], %1;"
                 :: "r"(mbar), "r"(bytes) : "memory");
}
__device__ __forceinline__ void bulk_g2s(uint32_t dst, const void* src,
                                         uint32_t bytes, uint32_t mbar) {
    asm volatile("cp.async.bulk.shared::cta.global.mbarrier::complete_tx::bytes "
                 "[%0], [%1], %2, [%3];"
                 :: "r"(dst), "l"(src), "r"(bytes), "r"(mbar) : "memory");
}
__device__ __forceinline__ void mbar_wait(uint32_t mbar, uint32_t parity) {
    uint32_t done;
    asm volatile(
        "{\n\t.reg .pred p;\n\t"
        "mbarrier.try_wait.parity.acquire.cta.shared::cta.b64 p, [%1], %2;\n\t"
        "selp.b32 %0, 1, 0, p;\n\t}"
        : "=r"(done) : "r"(mbar), "r"(parity) : "memory");
    if (!done) {
        asm volatile(
            "{\n\t.reg .pred P1;\n\t"
            "WAIT_LOOP_%=:\n\t"
            "mbarrier.try_wait.parity.acquire.cta.shared::cta.b64 P1, [%0], %1, 0x989680;\n\t"
            "@P1 bra.uni WAIT_DONE_%=;\n\t"
            "bra.uni WAIT_LOOP_%=;\n\t"
            "WAIT_DONE_%=:\n\t}"
            :: "r"(mbar), "r"(parity) : "memory");
    }
}

// Warp-cooperative lower_bound: smallest i with a[i] >= v. All 32 lanes participate.
__device__ __forceinline__ int warp_lower_bound(const int* __restrict__ a,
                                                int n, int v, int lane)
{
    int lo = 0, hi = n;
    while (hi - lo > 32) {
        const int chunk = (hi - lo + 32) / 33;
        const int p  = lo + (lane + 1) * chunk;
        const int pv = (p < hi) ? __ldg(a + p) : 0x7fffffff;
        const unsigned m = __ballot_sync(0xffffffffu, pv < v);
        const int c = __popc(m);
        const int nlo = lo + c * chunk;
        hi = min(hi, nlo + chunk);
        lo = nlo;
    }
    const int p  = lo + lane;
    const int pv = (p < hi) ? __ldg(a + p) : 0x7fffffff;
    const unsigned m = __ballot_sync(0xffffffffu, pv < v);
    return lo + __popc(m);
}

__global__ __launch_bounds__(NTHREADS, 4) void trf_fold_kernel(
    const float4* __restrict__ TRF4,
    const int*    __restrict__ sIdx,
    float*        __restrict__ out,
    int nSeq, int nWin, int nRealLen)
{
    __shared__ __align__(128) char raw[NSTAGE * STAGE_B];   // stages; transpose aliases later
    __shared__ __align__(8)  uint64_t mbar_store[NSTAGE];
    __shared__ int s_on[CHUNK];
    __shared__ int s_range[2];

    const int t0   = blockIdx.x * TILE_T;
    const int tid  = threadIdx.x;
    const int w    = tid >> 5;
    const int lane = tid & 31;

    const uint32_t stg_u32  = (uint32_t)__cvta_generic_to_shared(raw);
    const uint32_t mbar_u32 = (uint32_t)__cvta_generic_to_shared(mbar_store);

    if (tid == 0) {
        #pragma unroll
        for (int q = 0; q < NSTAGE; ++q) mbar_init(mbar_u32 + q * 8, 1);
    }

    // ---- per-CTA range: warps 1 and 2 search (warp 0 reserved for nothing; overlap init)
    if (w == 1) {
        int lo = warp_lower_bound(sIdx, nSeq, t0 - nWin + 1, lane);
        if (lane == 0) s_range[0] = lo;
    } else if (w == 2) {
        int hi = warp_lower_bound(sIdx, nSeq, t0 + TILE_T, lane);
        if (lane == 0) s_range[1] = hi;
    }
    __syncthreads();                         // mbar init + ranges visible
    const int seqLo = s_range[0];
    const int seqHi = s_range[1];

    float4 acc[ROWS_PW];
    #pragma unroll
    for (int r = 0; r < ROWS_PW; ++r) acc[r] = make_float4(0.f, 0.f, 0.f, 0.f);

    const unsigned f4Row = OUTD / 4;         // 32 float4 per row
    const float4* stg = reinterpret_cast<const float4*>(raw);

    int ph[NSTAGE] = {0, 0, 0};              // per-thread parity per stage
    int ibase = 0;                           // global seq counter -> ring position

    for (int cbase = seqLo; cbase < seqHi; cbase += CHUNK) {
        const int cn = min(seqHi - cbase, CHUNK);
        if (tid < cn) s_on[tid] = sIdx[cbase + tid];
        __syncthreads();                     // s_on visible; prior stage reads done

        // producer: issue one bulk copy for local seq q into stage (ibase+q)%NSTAGE
        auto issue = [&](int q) {
            const int s   = s_on[q];
            const int klo = max(0, t0 - s);
            const int khi = min(nWin - 1, t0 + TILE_T - 1 - s);
            const uint32_t bytes = (uint32_t)(khi - klo + 1) << 9;     // rows*512
            const int st = (ibase + q) % NSTAGE;
            const unsigned srcIdx = (unsigned)(cbase + q) * (unsigned)nWin * f4Row
                                  + (unsigned)klo * f4Row;             // klo>=0, no wrap
            mbar_expect_tx(mbar_u32 + st * 8, bytes);
            bulk_g2s(stg_u32 + st * STAGE_B, TRF4 + srcIdx, bytes, mbar_u32 + st * 8);
        };

        if (tid == 0) {
            if (cn > 0) issue(0);
            if (cn > 1) issue(1);
        }

        for (int j = 0; j < cn; ++j) {
            if (tid == 0 && j + 2 < cn) issue(j + 2);

            const int st = (ibase + j) % NSTAGE;
            mbar_wait(mbar_u32 + st * 8, (uint32_t)ph[st]);
            ph[st] ^= 1;

            const int s   = s_on[j];
            const int klo = max(0, t0 - s);
            const float4* buf = stg + st * (STAGE_B / 16);
            #pragma unroll
            for (int r = 0; r < ROWS_PW; ++r) {
                const int k = t0 + w + 8 * r - s;
                if ((unsigned)k < (unsigned)nWin) {
                    const float4 v = buf[(k - klo) * 32 + lane];
                    acc[r].x += v.x; acc[r].y += v.y;
                    acc[r].z += v.z; acc[r].w += v.w;
                }
            }
            __syncthreads();                 // all reads of stage st done before reuse
        }
        ibase += cn;
    }

    // ---- transpose: reuse stage smem (all stages consumed; barrier above) ----
    float* sm = reinterpret_cast<float*>(raw);
    #pragma unroll
    for (int r = 0; r < ROWS_PW; ++r)
        *reinterpret_cast<float4*>(sm + (w + 8 * r) * ROWSTRIDE + lane * 4) = acc[r];
    __syncthreads();

    // ---- coalesced streaming store: consecutive tid -> consecutive t per d-row ----
    #pragma unroll
    for (int idx = tid; idx < OUTD * TILE_T; idx += NTHREADS) {
        const int d  = idx >> 5;              // / TILE_T
        const int tt = idx & (TILE_T - 1);
        const int t  = t0 + tt;
        if (t < nRealLen)
            __stcs(&out[(size_t)d * nRealLen + t], sm[tt * ROWSTRIDE + d]);
    }
}

extern "C" void kernel_launch(void* const* d_in, const int* in_sizes, int n_in,
                              void* d_out, int out_size)
{
    const float4* TRF4 = (const float4*)d_in[0];
    const int*    sIdx = (const int*)d_in[1];
    const int nSeq     = in_sizes[1];
    const int nWin     = in_sizes[0] / (nSeq * OUTD);
    const int nRealLen = out_size / OUTD;

    const int grid = (nRealLen + TILE_T - 1) / TILE_T;
    trf_fold_kernel<<<grid, NTHREADS>>>(TRF4, sIdx, (float*)d_out,
                                        nSeq, nWin, nRealLen);
}

// round 17
// speedup vs baseline: 1.0381x; 1.0381x over previous
#include <cuda_runtime.h>
#include <cstdint>

// TRFAligner: out[d, t] = sum over (seq, k) with sourceIdx[seq] + k == t of TRFs[seq, k, d]
// TRFs: (nSeq, nWin, OUTD) fp32; out: (OUTD, nRealLen) fp32. sourceIdx sorted.
// R14 base (best): TILE_T=32 / 256 threads / 4 rows per warp, cp.async (LDGSTS)
// double-buffered barrier-free pipeline (each thread consumes only its own slots),
// 32-bit unsigned element indexing (negative-kb wrap cancels before pointer add).
// NEW: vectorized epilogue — 4x(4 LDS + STG.128) instead of 16x(LDS + STG.32).
// No atomics.

#define OUTD      128
#define TILE_T    32
#define ROWSTRIDE 132                 // transpose tile row stride (floats)
#define NWARPS    8
#define NTHREADS  (NWARPS * 32)
#define ROWS_PW   (TILE_T / NWARPS)   // 4 rows per warp: tt = w + 8*r
#define CHUNK     64
#define STAGE_B   (TILE_T * 32 * 16)  // 32 rows * 512B = 16384 bytes per stage

__device__ __forceinline__ void cp_async16(uint32_t dst, const void* src, int sz) {
    asm volatile("cp.async.cg.shared.global [%0], [%1], 16, %2;\n"
                 :: "r"(dst), "l"(src), "r"(sz));
}
#define CP_COMMIT() asm volatile("cp.async.commit_group;\n" ::: "memory")
#define CP_WAIT(N)  asm volatile("cp.async.wait_group %0;\n" :: "n"(N) : "memory")

// Warp-cooperative lower_bound: smallest i with a[i] >= v. All 32 lanes participate.
__device__ __forceinline__ int warp_lower_bound(const int* __restrict__ a,
                                                int n, int v, int lane)
{
    int lo = 0, hi = n;
    while (hi - lo > 32) {
        const int chunk = (hi - lo + 32) / 33;
        const int p  = lo + (lane + 1) * chunk;
        const int pv = (p < hi) ? __ldg(a + p) : 0x7fffffff;
        const unsigned m = __ballot_sync(0xffffffffu, pv < v);
        const int c = __popc(m);
        const int nlo = lo + c * chunk;
        hi = min(hi, nlo + chunk);
        lo = nlo;
    }
    const int p  = lo + lane;
    const int pv = (p < hi) ? __ldg(a + p) : 0x7fffffff;
    const unsigned m = __ballot_sync(0xffffffffu, pv < v);
    return lo + __popc(m);
}

__global__ __launch_bounds__(NTHREADS, 6) void trf_fold_kernel(
    const float4* __restrict__ TRF4,
    const int*    __restrict__ sIdx,
    float*        __restrict__ out,
    int nSeq, int nWin, int nRealLen)
{
    // 2 cp.async stages; the transpose tile (32*132*4 = 16896B) aliases them later.
    __shared__ __align__(16) char raw[2 * STAGE_B];
    __shared__ int s_on[CHUNK];
    __shared__ int s_range[2];

    const int t0   = blockIdx.x * TILE_T;
    const int tid  = threadIdx.x;
    const int w    = tid >> 5;
    const int lane = tid & 31;

    const uint32_t stg_u32 = (uint32_t)__cvta_generic_to_shared(raw);
    uint32_t slot[ROWS_PW];               // this thread's 4 stage slots, 16B each
    #pragma unroll
    for (int r = 0; r < ROWS_PW; ++r)
        slot[r] = stg_u32 + (((w + 8 * r) * 32 + lane) << 4);

    // ---- per-CTA range: warps 0 and 1 search concurrently ----
    if (w == 0) {
        int lo = warp_lower_bound(sIdx, nSeq, t0 - nWin + 1, lane);
        if (lane == 0) s_range[0] = lo;
    } else if (w == 1) {
        int hi = warp_lower_bound(sIdx, nSeq, t0 + TILE_T, lane);
        if (lane == 0) s_range[1] = hi;
    }
    __syncthreads();
    const int seqLo = s_range[0];
    const int seqHi = s_range[1];

    float4 acc[ROWS_PW];
    #pragma unroll
    for (int r = 0; r < ROWS_PW; ++r) acc[r] = make_float4(0.f, 0.f, 0.f, 0.f);

    const unsigned f4Row     = OUTD / 4;
    const unsigned seqStride = (unsigned)nWin * f4Row;
    const float4* stg = reinterpret_cast<const float4*>(raw);   // [2][1024] float4

    for (int cbase = seqLo; cbase < seqHi; cbase += CHUNK) {
        const int cn = min(seqHi - cbase, CHUNK);
        __syncthreads();                                 // protect s_on + stage reuse
        if (tid < cn) s_on[tid] = sIdx[cbase + tid];
        __syncthreads();

        // prologue: issue seq 0 into stage 0
        {
            const int kb = t0 + w - s_on[0];
            const unsigned off = (unsigned)cbase * seqStride
                               + (unsigned)kb * f4Row + (unsigned)lane;
            #pragma unroll
            for (int r = 0; r < ROWS_PW; ++r) {
                const bool p = (unsigned)(kb + 8 * r) < (unsigned)nWin;
                const unsigned idx = off + (unsigned)(r * 8) * f4Row;  // 32-bit wrap cancels
                const float4* src = p ? (TRF4 + idx) : TRF4;
                cp_async16(slot[r], src, p ? 16 : 0);
            }
            CP_COMMIT();
        }

        for (int j = 0; j < cn; ++j) {
            if (j + 1 < cn) {
                const int kb = t0 + w - s_on[j + 1];
                const unsigned off = (unsigned)(cbase + j + 1) * seqStride
                                   + (unsigned)kb * f4Row + (unsigned)lane;
                const uint32_t sb = ((j + 1) & 1) * STAGE_B;
                #pragma unroll
                for (int r = 0; r < ROWS_PW; ++r) {
                    const bool p = (unsigned)(kb + 8 * r) < (unsigned)nWin;
                    const unsigned idx = off + (unsigned)(r * 8) * f4Row;
                    const float4* src = p ? (TRF4 + idx) : TRF4;
                    cp_async16(slot[r] + sb, src, p ? 16 : 0);
                }
                CP_COMMIT();
                CP_WAIT(1);                 // stage j complete, stage j+1 in flight
            } else {
                CP_WAIT(0);                 // drain
            }
            // accumulate stage j (zero-filled where out of window -> unguarded)
            const float4* buf = stg + (j & 1) * (STAGE_B / 16);
            #pragma unroll
            for (int r = 0; r < ROWS_PW; ++r) {
                const float4 v = buf[(w + 8 * r) * 32 + lane];
                acc[r].x += v.x; acc[r].y += v.y;
                acc[r].z += v.z; acc[r].w += v.w;
            }
        }
    }

    // ---- transpose: reuse stage smem (all pipeline reads done; barrier first) ----
    __syncthreads();
    float* sm = reinterpret_cast<float*>(raw);
    #pragma unroll
    for (int r = 0; r < ROWS_PW; ++r)
        *reinterpret_cast<float4*>(sm + (w + 8 * r) * ROWSTRIDE + lane * 4) = acc[r];
    __syncthreads();

    // ---- vectorized epilogue: each task = (d, group of 4 consecutive t) ----
    // 128 d-rows * 8 groups = 1024 tasks, 4 per thread; one STG.128 per task.
    #pragma unroll
    for (int idx = tid; idx < OUTD * (TILE_T / 4); idx += NTHREADS) {
        const int d = idx >> 3;               // / (TILE_T/4)
        const int g = idx & 7;
        const int t = t0 + g * 4;
        float4 v;
        v.x = sm[(g * 4 + 0) * ROWSTRIDE + d];
        v.y = sm[(g * 4 + 1) * ROWSTRIDE + d];
        v.z = sm[(g * 4 + 2) * ROWSTRIDE + d];
        v.w = sm[(g * 4 + 3) * ROWSTRIDE + d];
        if (t + 3 < nRealLen) {
            __stcs(reinterpret_cast<float4*>(out + (size_t)d * nRealLen + t), v);
        } else {                              // ragged tail (not hit for 100000)
            const float vv[4] = {v.x, v.y, v.z, v.w};
            for (int c = 0; c < 4; ++c)
                if (t + c < nRealLen) out[(size_t)d * nRealLen + t + c] = vv[c];
        }
    }
}

extern "C" void kernel_launch(void* const* d_in, const int* in_sizes, int n_in,
                              void* d_out, int out_size)
{
    const float4* TRF4 = (const float4*)d_in[0];
    const int*    sIdx = (const int*)d_in[1];
    const int nSeq     = in_sizes[1];
    const int nWin     = in_sizes[0] / (nSeq * OUTD);
    const int nRealLen = out_size / OUTD;

    const int grid = (nRealLen + TILE_T - 1) / TILE_T;
    trf_fold_kernel<<<grid, NTHREADS>>>(TRF4, sIdx, (float*)d_out,
                                        nSeq, nWin, nRealLen);
}